// round 1
// baseline (speedup 1.0000x reference)
#include <cuda_runtime.h>
#include <cuda_bf16.h>
#include <cstddef>

// Problem constants (fixed shapes from setup_inputs)
#define NT   9216      // H*W
#define LCH  21        // label channels
#define BB   2         // batch
#define MT   384       // GEMM k-tile (divides 9216: 24 tiles)
#define MPAD 28        // padded L stride for M buffer (bank-conflict-free, 16B aligned)
#define NITERS 5

// ---- device scratch (no allocation allowed) ----
__device__ float g_A[(size_t)BB * NT * NT];   // unnormalized affinity exp(-0.5 D), 679 MB
__device__ float g_inv[BB * NT];              // 1 / rowsum
__device__ float g_M[(size_t)BB * NT * MPAD]; // M^T padded: [b][m][k], k<21 valid
__device__ float g_pot[(size_t)BB * LCH * NT];// E0 + msg

// ============================================================================
// Kernel 1: affinity rows + rowsum.  32 rows per block, 576 blocks.
// A[b,n,m] = exp(-0.5 * (|f_n|^2 + |f_m|^2 - 2 f_n.f_m)), rowsum reciprocal to g_inv.
// ============================================================================
__global__ void k_affinity(const float* __restrict__ Refs) {
    __shared__ float4 rf[32];        // (x,y,z,|f|^2) for the 32 rows of this block
    __shared__ float  wsum[8][33];   // per-warp row partials (padded)

    const int tid = threadIdx.x;
    const int R   = blockIdx.x * 32;
    const int b   = R / NT;
    const int n0  = R - b * NT;
    const float* F = Refs + (size_t)b * 3 * NT;

    if (tid < 32) {
        int n = n0 + tid;
        float x = F[n], y = F[NT + n], z = F[2 * NT + n];
        rf[tid] = make_float4(x, y, z, x * x + y * y + z * z);
    }
    __syncthreads();

    float part[32];
#pragma unroll
    for (int r = 0; r < 32; r++) part[r] = 0.f;

    float* Abase = g_A + (size_t)(b * NT + n0) * NT;

    for (int m = tid; m < NT; m += 256) {
        float x = F[m], y = F[NT + m], z = F[2 * NT + m];
        float sq = x * x + y * y + z * z;
#pragma unroll
        for (int r = 0; r < 32; r++) {
            float4 f = rf[r];   // broadcast LDS (conflict-free)
            float d = f.w + sq - 2.f * (x * f.x + y * f.y + z * f.z);
            float e = __expf(-0.5f * d);
            Abase[(size_t)r * NT + m] = e;  // coalesced across threads
            part[r] += e;
        }
    }

    const int lane = tid & 31, w = tid >> 5;
#pragma unroll
    for (int r = 0; r < 32; r++) {
        float v = part[r];
#pragma unroll
        for (int off = 16; off; off >>= 1) v += __shfl_down_sync(0xffffffffu, v, off);
        if (lane == 0) wsum[w][r] = v;
    }
    __syncthreads();
    if (tid < 32) {
        float s = 0.f;
#pragma unroll
        for (int w2 = 0; w2 < 8; w2++) s += wsum[w2][tid];  // deterministic order
        g_inv[b * NT + n0 + tid] = 1.f / s;
    }
}

// ============================================================================
// Kernel 2: per-pixel softmax over L, then M = Mu @ Q (optionally), Q out (optionally).
// pot_ext == nullptr -> read g_pot.  18432 pixels, 72 blocks x 256 threads.
// ============================================================================
__global__ void k_softmax(const float* __restrict__ pot_ext,
                          const float* __restrict__ Mu,
                          int writeM, float* __restrict__ Qout) {
    __shared__ float mu[LCH * LCH];
    const int tid = threadIdx.x;
    for (int i = tid; i < LCH * LCH; i += 256) mu[i] = Mu[i];
    __syncthreads();

    const int pix = blockIdx.x * 256 + tid;
    const int b = pix / NT;
    const int n = pix - b * NT;

    const float* p = (pot_ext ? pot_ext : (const float*)g_pot) + (size_t)b * LCH * NT + n;

    float v[LCH];
    float mn = 3.4e38f;
#pragma unroll
    for (int l = 0; l < LCH; l++) { v[l] = p[(size_t)l * NT]; mn = fminf(mn, v[l]); }
    float s = 0.f;
#pragma unroll
    for (int l = 0; l < LCH; l++) { v[l] = __expf(mn - v[l]); s += v[l]; }
    float is = 1.f / s;
#pragma unroll
    for (int l = 0; l < LCH; l++) v[l] *= is;

    if (Qout) {
        float* q = Qout + (size_t)b * LCH * NT + n;
#pragma unroll
        for (int l = 0; l < LCH; l++) q[(size_t)l * NT] = v[l];
    }
    if (writeM) {
        float* Md = g_M + ((size_t)b * NT + n) * MPAD;
#pragma unroll
        for (int k = 0; k < LCH; k++) {
            float a = 0.f;
#pragma unroll
            for (int l = 0; l < LCH; l++) a = fmaf(mu[k * LCH + l], v[l], a);
            Md[k] = a;
        }
    }
}

// ============================================================================
// Kernel 3: skinny GEMM + epilogue.
// pot[b,l,n] = E0[b,l,n] + inv[n] * sum_m A[b,n,m] * M[b,m,l]
// Block: 256 thr = 32 m-lanes x 8 rowgroups; each thread: 4 rows x 21 cols accum.
// 576 blocks (32 rows each), 24 k-tiles of 384 staged in smem (stride 28 floats).
// ============================================================================
__global__ __launch_bounds__(256, 2) void k_gemm(const float* __restrict__ E0) {
    __shared__ float4 Ms[MT * (MPAD / 4)];  // [MT][7] float4

    const int tid  = threadIdx.x;
    const int lane = tid & 31;
    const int rg   = tid >> 5;            // 0..7
    const int R    = blockIdx.x * 32;
    const int b    = R / NT;
    const int n0   = R - b * NT;
    const int rowb = n0 + rg * 4;

    const float* A0 = g_A + (size_t)(b * NT + rowb) * NT;
    const float* A1 = A0 + NT;
    const float* A2 = A1 + NT;
    const float* A3 = A2 + NT;
    const float4* Mg = (const float4*)(g_M + (size_t)b * NT * MPAD);

    float acc[4][LCH];
#pragma unroll
    for (int i = 0; i < 4; i++)
#pragma unroll
        for (int l = 0; l < LCH; l++) acc[i][l] = 0.f;

    for (int t = 0; t < NT / MT; t++) {
        const int m0 = t * MT;
        const float4* src = Mg + (size_t)m0 * (MPAD / 4);
        for (int i = tid; i < MT * (MPAD / 4); i += 256) Ms[i] = src[i];
        __syncthreads();

#pragma unroll 1
        for (int s = 0; s < MT / 32; s++) {
            const int mm = s * 32 + lane;
            float a0 = A0[m0 + mm];
            float a1 = A1[m0 + mm];
            float a2 = A2[m0 + mm];
            float a3 = A3[m0 + mm];
            const float4* mp = Ms + mm * (MPAD / 4);
            float4 q0 = mp[0], q1 = mp[1], q2 = mp[2], q3 = mp[3], q4 = mp[4];
            float q5x = ((const float*)(mp + 5))[0];
            float mv[LCH] = { q0.x, q0.y, q0.z, q0.w,
                              q1.x, q1.y, q1.z, q1.w,
                              q2.x, q2.y, q2.z, q2.w,
                              q3.x, q3.y, q3.z, q3.w,
                              q4.x, q4.y, q4.z, q4.w,
                              q5x };
#pragma unroll
            for (int l = 0; l < LCH; l++) {
                float m = mv[l];
                acc[0][l] = fmaf(a0, m, acc[0][l]);
                acc[1][l] = fmaf(a1, m, acc[1][l]);
                acc[2][l] = fmaf(a2, m, acc[2][l]);
                acc[3][l] = fmaf(a3, m, acc[3][l]);
            }
        }
        __syncthreads();
    }

    // reduce across 32 m-lanes (intra-warp), epilogue by lane 0
#pragma unroll
    for (int i = 0; i < 4; i++) {
        const int n = rowb + i;
        const float iv = g_inv[b * NT + n];
#pragma unroll
        for (int l = 0; l < LCH; l++) {
            float v = acc[i][l];
#pragma unroll
            for (int off = 16; off; off >>= 1) v += __shfl_down_sync(0xffffffffu, v, off);
            if (lane == 0) {
                size_t o = ((size_t)b * LCH + l) * NT + n;
                g_pot[o] = E0[o] + iv * v;
            }
        }
    }
}

// ============================================================================
extern "C" void kernel_launch(void* const* d_in, const int* in_sizes, int n_in,
                              void* d_out, int out_size) {
    const float* E0   = (const float*)d_in[0];
    const float* Refs = (const float*)d_in[1];
    const float* Mu   = (const float*)d_in[2];
    float* out = (float*)d_out;

    // 1) build affinity + row sums (recomputed each call; deterministic)
    k_affinity<<<(BB * NT) / 32, 256>>>(Refs);

    // 2) Q0 = softmax(-E0); M0 = Mu @ Q0
    k_softmax<<<(BB * NT) / 256, 256>>>(E0, Mu, 1, nullptr);

    // 3) mean-field iterations
    for (int it = 0; it < NITERS; it++) {
        k_gemm<<<(BB * NT) / 32, 256>>>(E0);
        k_softmax<<<(BB * NT) / 256, 256>>>(nullptr, Mu,
                                            (it < NITERS - 1) ? 1 : 0,
                                            (it == NITERS - 1) ? out : nullptr);
    }
}

// round 4
// speedup vs baseline: 4.7916x; 4.7916x over previous
#include <cuda_runtime.h>
#include <cuda_bf16.h>
#include <cstdint>
#include <cstddef>

#define NT    9216
#define LCH   21
#define BB    2
#define NITERS 5
#define LROWS 24          // padded label rows for MMA (3 x n8)
#define KSTEPS (NT / 32)  // 288 k32 supersteps
#define PF    4           // prefetch depth

// ---------------- device scratch (no allocation allowed) ----------------
__device__ __nv_bfloat16 g_Abf[(size_t)BB * NT * NT];   // ~324 MB, row-major [n][m]
__device__ float         g_inv[BB * NT];                // 1 / rowsum
__device__ __nv_bfloat16 g_Mt[(size_t)BB * LROWS * NT]; // [b][l][m], rows 21..23 zero

// ---------------- fast exp2 on the FMA pipe (no MUFU) ----------------
// returns 2^y for y in [-80, 0.6]; rel err ~4e-5
__device__ __forceinline__ float fexp2(float y) {
    float r = y + 12582912.0f;              // round-to-nearest int into mantissa
    float f = y - (r - 12582912.0f);        // f in [-0.5, 0.5]
    int   n = __float_as_int(r);            // 0x4B400000 + n
    float s = __int_as_float((n + (127 - 0x4B400000)) << 23);  // 2^n
    float p = fmaf(0.00961813f, f, 0.05550411f);
    p = fmaf(p, f, 0.24022651f);
    p = fmaf(p, f, 0.69314718f);
    p = fmaf(p, f, 1.0f);
    return p * s;
}

// ============================================================================
// Kernel 1: affinity (bf16) + rowsum reciprocal. 32 rows / block, 576 blocks.
// A[n,m] = exp(-0.5(|fn|^2+|fm|^2-2fn.fm)) ; exp via 2^y, y = 1.4427*dot + base
// ============================================================================
__global__ __launch_bounds__(256) void k_affinity(const float* __restrict__ Refs) {
    __shared__ float4 rf[32];        // (x, y, z, -0.72134752*|f|^2)
    __shared__ float  wsum[8][33];
    const int tid = threadIdx.x;
    const int R = blockIdx.x * 32;
    const int b = R / NT;
    const int n0 = R - b * NT;
    const float* F = Refs + (size_t)b * 3 * NT;

    if (tid < 32) {
        int n = n0 + tid;
        float x = F[n], y = F[NT + n], z = F[2 * NT + n];
        rf[tid] = make_float4(x, y, z, -0.72134752f * (x * x + y * y + z * z));
    }
    __syncthreads();

    float part[32];
#pragma unroll
    for (int r = 0; r < 32; r++) part[r] = 0.f;

    for (int m2 = tid; m2 < NT / 2; m2 += 256) {
        int m = m2 * 2;
        float x0 = F[m],     y0 = F[NT + m],     z0 = F[2 * NT + m];
        float x1 = F[m + 1], y1 = F[NT + m + 1], z1 = F[2 * NT + m + 1];
        float sc0 = -0.72134752f * (x0 * x0 + y0 * y0 + z0 * z0);
        float sc1 = -0.72134752f * (x1 * x1 + y1 * y1 + z1 * z1);
#pragma unroll
        for (int r = 0; r < 32; r++) {
            float4 f = rf[r];
            float d0 = x0 * f.x + y0 * f.y + z0 * f.z;
            float d1 = x1 * f.x + y1 * f.y + z1 * f.z;
            float e0 = fexp2(fmaf(d0, 1.44269504f, f.w + sc0));
            float e1 = fexp2(fmaf(d1, 1.44269504f, f.w + sc1));
            ((__nv_bfloat162*)(g_Abf + (size_t)(b * NT + n0 + r) * NT))[m2] =
                __floats2bfloat162_rn(e0, e1);
            part[r] += e0 + e1;
        }
    }

    const int lane = tid & 31, w = tid >> 5;
#pragma unroll
    for (int r = 0; r < 32; r++) {
        float v = part[r];
#pragma unroll
        for (int off = 16; off; off >>= 1) v += __shfl_down_sync(0xffffffffu, v, off);
        if (lane == 0) wsum[w][r] = v;
    }
    __syncthreads();
    if (tid < 32) {
        float s = 0.f;
#pragma unroll
        for (int w2 = 0; w2 < 8; w2++) s += wsum[w2][tid];
        g_inv[b * NT + n0 + tid] = 1.f / s;
    }
}

// ============================================================================
// Kernel 2: initial softmax + Potts mix:  Mt = Mu @ softmax(-E0)  (bf16)
// Zeroes Mt rows 21..23 (padding for the N=24 MMA).
// ============================================================================
__global__ __launch_bounds__(256) void k_softmax0(const float* __restrict__ E0,
                                                  const float* __restrict__ Mu) {
    __shared__ float mu[LCH * LCH];
    const int tid = threadIdx.x;
    for (int i = tid; i < LCH * LCH; i += 256) mu[i] = Mu[i];
    __syncthreads();

    const int pix = blockIdx.x * 256 + tid;
    const int b = pix / NT;
    const int n = pix - b * NT;
    const float* p = E0 + (size_t)b * LCH * NT + n;

    float v[LCH], mn = 3.4e38f;
#pragma unroll
    for (int l = 0; l < LCH; l++) { v[l] = p[(size_t)l * NT]; mn = fminf(mn, v[l]); }
    float s = 0.f;
#pragma unroll
    for (int l = 0; l < LCH; l++) { v[l] = fexp2(1.44269504f * (mn - v[l])); s += v[l]; }
    float is = 1.f / s;
#pragma unroll
    for (int l = 0; l < LCH; l++) v[l] *= is;

#pragma unroll
    for (int k = 0; k < LCH; k++) {
        float a = 0.f;
#pragma unroll
        for (int l = 0; l < LCH; l++) a = fmaf(mu[k * LCH + l], v[l], a);
        g_Mt[((size_t)b * LROWS + k) * NT + n] = __float2bfloat16(a);
    }
    const __nv_bfloat16 z = __float2bfloat16(0.f);
#pragma unroll
    for (int k = LCH; k < LROWS; k++) g_Mt[((size_t)b * LROWS + k) * NT + n] = z;
}

// ---------------- warp-level bf16 MMA (sm_80+, no 'a' gating) ----------------
__device__ __forceinline__ void mma16816(float& c0, float& c1, float& c2, float& c3,
                                         uint32_t a0, uint32_t a1, uint32_t a2, uint32_t a3,
                                         uint32_t b0, uint32_t b1) {
    asm volatile(
        "mma.sync.aligned.m16n8k16.row.col.f32.bf16.bf16.f32 "
        "{%0,%1,%2,%3}, {%4,%5,%6,%7}, {%8,%9}, {%0,%1,%2,%3};"
        : "+f"(c0), "+f"(c1), "+f"(c2), "+f"(c3)
        : "r"(a0), "r"(a1), "r"(a2), "r"(a3), "r"(b0), "r"(b1));
}

// ============================================================================
// Kernel 3: one mean-field iteration via HMMA.
// D[128,24] = A_rows(bf16) x Mt^T ; fused epilogue: pot = E0 + inv*D,
// Q = softmax(-pot), Mt = Mu@Q (or write out on last iter).
// K-axis relabeled so every fragment load is one contiguous LDG.128/thread.
// 144 CTAs x 256 thr (8 warps x 16 rows). 4-deep register prefetch pipeline.
// ============================================================================
__global__ __launch_bounds__(256, 1) void k_iter(const float* __restrict__ E0,
                                                 const float* __restrict__ Mu,
                                                 float* __restrict__ out, int last) {
    __shared__ float Ds[128][25];     // D transpose buffer (pad 25: conflict-free)
    __shared__ float mu_s[LCH * LCH];

    const int tid = threadIdx.x;
    const int wid = tid >> 5, lane = tid & 31;
    const int g = lane >> 2, q = lane & 3;
    const int b  = blockIdx.x / (NT / 128);
    const int nb = (blockIdx.x - b * (NT / 128)) * 128;

    for (int i = tid; i < LCH * LCH; i += 256) mu_s[i] = Mu[i];

    // per-thread fragment pointers (int4 = 16 bytes = 8 bf16 = one k8 run)
    const int rowA = nb + 16 * wid + g;
    const int4* Ap0 = (const int4*)(g_Abf + (size_t)(b * NT + rowA) * NT) + q;
    const int4* Ap1 = (const int4*)(g_Abf + (size_t)(b * NT + rowA + 8) * NT) + q;
    const int4* Bp0 = (const int4*)(g_Mt + (size_t)(b * LROWS + g)      * NT) + q;
    const int4* Bp1 = (const int4*)(g_Mt + (size_t)(b * LROWS + 8 + g)  * NT) + q;
    const int4* Bp2 = (const int4*)(g_Mt + (size_t)(b * LROWS + 16 + g) * NT) + q;

    float4 acc[3];
#pragma unroll
    for (int t = 0; t < 3; t++) acc[t] = make_float4(0.f, 0.f, 0.f, 0.f);

    int4 a0b[PF], a1b[PF], b0b[PF], b1b[PF], b2b[PF];
#pragma unroll
    for (int p = 0; p < PF; p++) {
        a0b[p] = Ap0[p * 4]; a1b[p] = Ap1[p * 4];
        b0b[p] = Bp0[p * 4]; b1b[p] = Bp1[p * 4]; b2b[p] = Bp2[p * 4];
    }

    for (int s = 0; s < KSTEPS; s += PF) {
#pragma unroll
        for (int p = 0; p < PF; p++) {
            const uint32_t* A0 = (const uint32_t*)&a0b[p];
            const uint32_t* A1 = (const uint32_t*)&a1b[p];
            const uint32_t* B0 = (const uint32_t*)&b0b[p];
            const uint32_t* B1 = (const uint32_t*)&b1b[p];
            const uint32_t* B2 = (const uint32_t*)&b2b[p];
            // f = 0 (k-labels from first 8B), f = 1 (second 8B)
            mma16816(acc[0].x, acc[0].y, acc[0].z, acc[0].w,
                     A0[0], A1[0], A0[1], A1[1], B0[0], B0[1]);
            mma16816(acc[1].x, acc[1].y, acc[1].z, acc[1].w,
                     A0[0], A1[0], A0[1], A1[1], B1[0], B1[1]);
            mma16816(acc[2].x, acc[2].y, acc[2].z, acc[2].w,
                     A0[0], A1[0], A0[1], A1[1], B2[0], B2[1]);
            mma16816(acc[0].x, acc[0].y, acc[0].z, acc[0].w,
                     A0[2], A1[2], A0[3], A1[3], B0[2], B0[3]);
            mma16816(acc[1].x, acc[1].y, acc[1].z, acc[1].w,
                     A0[2], A1[2], A0[3], A1[3], B1[2], B1[3]);
            mma16816(acc[2].x, acc[2].y, acc[2].z, acc[2].w,
                     A0[2], A1[2], A0[3], A1[3], B2[2], B2[3]);
            int sn = s + p + PF;
            if (sn < KSTEPS) {
                a0b[p] = Ap0[sn * 4]; a1b[p] = Ap1[sn * 4];
                b0b[p] = Bp0[sn * 4]; b1b[p] = Bp1[sn * 4]; b2b[p] = Bp2[sn * 4];
            }
        }
    }

    // scatter fragments to smem: c0=(g,2q), c1=(g,2q+1), c2=(g+8,2q), c3=(g+8,2q+1)
    const int r0 = 16 * wid + g;
#pragma unroll
    for (int t = 0; t < 3; t++) {
        const int c = 8 * t + 2 * q;
        Ds[r0][c]     = acc[t].x;  Ds[r0][c + 1]     = acc[t].y;
        Ds[r0 + 8][c] = acc[t].z;  Ds[r0 + 8][c + 1] = acc[t].w;
    }
    __syncthreads();

    // ---- fused epilogue: 128 threads, one pixel each ----
    if (tid < 128) {
        const int n = nb + tid;
        const float inv = g_inv[b * NT + n];
        const float* e0p = E0 + (size_t)b * LCH * NT + n;

        float pot[LCH], mn = 3.4e38f;
#pragma unroll
        for (int l = 0; l < LCH; l++) {
            pot[l] = e0p[(size_t)l * NT] + Ds[tid][l] * inv;
            mn = fminf(mn, pot[l]);
        }
        float s = 0.f;
#pragma unroll
        for (int l = 0; l < LCH; l++) { pot[l] = fexp2(1.44269504f * (mn - pot[l])); s += pot[l]; }
        float is = 1.f / s;
#pragma unroll
        for (int l = 0; l < LCH; l++) pot[l] *= is;

        if (last) {
            float* o = out + (size_t)b * LCH * NT + n;
#pragma unroll
            for (int l = 0; l < LCH; l++) o[(size_t)l * NT] = pot[l];
        } else {
#pragma unroll
            for (int k = 0; k < LCH; k++) {
                float a = 0.f;
#pragma unroll
                for (int l = 0; l < LCH; l++) a = fmaf(mu_s[k * LCH + l], pot[l], a);
                g_Mt[((size_t)b * LROWS + k) * NT + n] = __float2bfloat16(a);
            }
        }
    }
}

// ============================================================================
extern "C" void kernel_launch(void* const* d_in, const int* in_sizes, int n_in,
                              void* d_out, int out_size) {
    const float* E0   = (const float*)d_in[0];
    const float* Refs = (const float*)d_in[1];
    const float* Mu   = (const float*)d_in[2];
    float* out = (float*)d_out;

    k_affinity<<<(BB * NT) / 32, 256>>>(Refs);
    k_softmax0<<<(BB * NT) / 256, 256>>>(E0, Mu);
    for (int it = 0; it < NITERS; it++)
        k_iter<<<BB * (NT / 128), 256>>>(E0, Mu, out, it == NITERS - 1);
}

// round 6
// speedup vs baseline: 5.8436x; 1.2195x over previous
#include <cuda_runtime.h>
#include <cuda_bf16.h>
#include <cstdint>
#include <cstddef>

#define NT    9216
#define LCH   21
#define BB    2
#define NITERS 5
#define LROWS 24           // padded label rows for MMA (3 x n8)
#define KSTEPS (NT / 32)   // 288 k32 supersteps
#define KHALF  (KSTEPS / 2)
#define PF    4            // prefetch depth (per warp-set)

// ---------------- device scratch (no allocation allowed) ----------------
__device__ __nv_bfloat16 g_Abf[(size_t)BB * NT * NT];   // ~324 MB, row-major [n][m]
__device__ float         g_inv[BB * NT];                // 1 / rowsum
__device__ __nv_bfloat16 g_Mt[(size_t)BB * LROWS * NT]; // [b][l][m], rows 21..23 zero

// ---------------- fast exp2 on the FMA pipe (no MUFU) ----------------
__device__ __forceinline__ float fexp2(float y) {
    float r = y + 12582912.0f;
    float f = y - (r - 12582912.0f);
    int   n = __float_as_int(r);
    float s = __int_as_float((n + (127 - 0x4B400000)) << 23);
    float p = fmaf(0.00961813f, f, 0.05550411f);
    p = fmaf(p, f, 0.24022651f);
    p = fmaf(p, f, 0.69314718f);
    p = fmaf(p, f, 1.0f);
    return p * s;
}

// ============================================================================
// Kernel 1: affinity (bf16) + rowsum reciprocal. 32 rows / block, 576 blocks.
// ============================================================================
__global__ __launch_bounds__(256) void k_affinity(const float* __restrict__ Refs) {
    __shared__ float4 rf[32];
    __shared__ float  wsum[8][33];
    const int tid = threadIdx.x;
    const int R = blockIdx.x * 32;
    const int b = R / NT;
    const int n0 = R - b * NT;
    const float* F = Refs + (size_t)b * 3 * NT;

    if (tid < 32) {
        int n = n0 + tid;
        float x = F[n], y = F[NT + n], z = F[2 * NT + n];
        rf[tid] = make_float4(x, y, z, -0.72134752f * (x * x + y * y + z * z));
    }
    __syncthreads();

    float part[32];
#pragma unroll
    for (int r = 0; r < 32; r++) part[r] = 0.f;

    for (int m2 = tid; m2 < NT / 2; m2 += 256) {
        int m = m2 * 2;
        float x0 = F[m],     y0 = F[NT + m],     z0 = F[2 * NT + m];
        float x1 = F[m + 1], y1 = F[NT + m + 1], z1 = F[2 * NT + m + 1];
        float sc0 = -0.72134752f * (x0 * x0 + y0 * y0 + z0 * z0);
        float sc1 = -0.72134752f * (x1 * x1 + y1 * y1 + z1 * z1);
#pragma unroll
        for (int r = 0; r < 32; r++) {
            float4 f = rf[r];
            float d0 = x0 * f.x + y0 * f.y + z0 * f.z;
            float d1 = x1 * f.x + y1 * f.y + z1 * f.z;
            float e0 = fexp2(fmaf(d0, 1.44269504f, f.w + sc0));
            float e1 = fexp2(fmaf(d1, 1.44269504f, f.w + sc1));
            ((__nv_bfloat162*)(g_Abf + (size_t)(b * NT + n0 + r) * NT))[m2] =
                __floats2bfloat162_rn(e0, e1);
            part[r] += e0 + e1;
        }
    }

    const int lane = tid & 31, w = tid >> 5;
#pragma unroll
    for (int r = 0; r < 32; r++) {
        float v = part[r];
#pragma unroll
        for (int off = 16; off; off >>= 1) v += __shfl_down_sync(0xffffffffu, v, off);
        if (lane == 0) wsum[w][r] = v;
    }
    __syncthreads();
    if (tid < 32) {
        float s = 0.f;
#pragma unroll
        for (int w2 = 0; w2 < 8; w2++) s += wsum[w2][tid];
        g_inv[b * NT + n0 + tid] = 1.f / s;
    }
}

// ============================================================================
// Kernel 2: initial softmax + Potts mix:  Mt = Mu @ softmax(-E0)  (bf16)
// ============================================================================
__global__ __launch_bounds__(256) void k_softmax0(const float* __restrict__ E0,
                                                  const float* __restrict__ Mu) {
    __shared__ float mu[LCH * LCH];
    const int tid = threadIdx.x;
    for (int i = tid; i < LCH * LCH; i += 256) mu[i] = Mu[i];
    __syncthreads();

    const int pix = blockIdx.x * 256 + tid;
    const int b = pix / NT;
    const int n = pix - b * NT;
    const float* p = E0 + (size_t)b * LCH * NT + n;

    float v[LCH], mn = 3.4e38f;
#pragma unroll
    for (int l = 0; l < LCH; l++) { v[l] = p[(size_t)l * NT]; mn = fminf(mn, v[l]); }
    float s = 0.f;
#pragma unroll
    for (int l = 0; l < LCH; l++) { v[l] = fexp2(1.44269504f * (mn - v[l])); s += v[l]; }
    float is = 1.f / s;
#pragma unroll
    for (int l = 0; l < LCH; l++) v[l] *= is;

#pragma unroll
    for (int k = 0; k < LCH; k++) {
        float a = 0.f;
#pragma unroll
        for (int l = 0; l < LCH; l++) a = fmaf(mu[k * LCH + l], v[l], a);
        g_Mt[((size_t)b * LROWS + k) * NT + n] = __float2bfloat16(a);
    }
    const __nv_bfloat16 z = __float2bfloat16(0.f);
#pragma unroll
    for (int k = LCH; k < LROWS; k++) g_Mt[((size_t)b * LROWS + k) * NT + n] = z;
}

// ---------------- warp-level bf16 MMA ----------------
__device__ __forceinline__ void mma16816(float& c0, float& c1, float& c2, float& c3,
                                         uint32_t a0, uint32_t a1, uint32_t a2, uint32_t a3,
                                         uint32_t b0, uint32_t b1) {
    asm volatile(
        "mma.sync.aligned.m16n8k16.row.col.f32.bf16.bf16.f32 "
        "{%0,%1,%2,%3}, {%4,%5,%6,%7}, {%8,%9}, {%0,%1,%2,%3};"
        : "+f"(c0), "+f"(c1), "+f"(c2), "+f"(c3)
        : "r"(a0), "r"(a1), "r"(a2), "r"(a3), "r"(b0), "r"(b1));
}

// ============================================================================
// Kernel 3: one mean-field iteration via HMMA, K-split x2 inside the CTA.
// 512 thr = 16 warps: warp-set (wid>>3) handles one K half (144 supersteps),
// partial D[128,24] tiles reduced via smem. Fused softmax+Potts epilogue.
// All prefetch loads unconditional (clamped index, no branch around LDGs).
// ============================================================================
__global__ __launch_bounds__(512, 1) void k_iter(const float* __restrict__ E0,
                                                 const float* __restrict__ Mu,
                                                 float* __restrict__ out, int last) {
    __shared__ float Ds[2][128][25];   // partial D per K-half (pad 25)
    __shared__ float mu_s[LCH * LCH];

    const int tid = threadIdx.x;
    const int wid = tid >> 5, lane = tid & 31;
    const int kset = wid >> 3, w8 = wid & 7;
    const int g = lane >> 2, q = lane & 3;
    const int b  = blockIdx.x / (NT / 128);
    const int nb = (blockIdx.x - b * (NT / 128)) * 128;

    for (int i = tid; i < LCH * LCH; i += 512) mu_s[i] = Mu[i];

    // per-thread fragment pointers; K-half offset = kset*KHALF supersteps (4 int4 each)
    const int rowA = nb + 16 * w8 + g;
    const int ko = kset * KHALF * 4 + q;
    const int4* Ap0 = (const int4*)(g_Abf + (size_t)(b * NT + rowA) * NT) + ko;
    const int4* Ap1 = (const int4*)(g_Abf + (size_t)(b * NT + rowA + 8) * NT) + ko;
    const int4* Bp0 = (const int4*)(g_Mt + (size_t)(b * LROWS + g)      * NT) + ko;
    const int4* Bp1 = (const int4*)(g_Mt + (size_t)(b * LROWS + 8 + g)  * NT) + ko;
    const int4* Bp2 = (const int4*)(g_Mt + (size_t)(b * LROWS + 16 + g) * NT) + ko;

    float4 acc[3];
#pragma unroll
    for (int t = 0; t < 3; t++) acc[t] = make_float4(0.f, 0.f, 0.f, 0.f);

    int4 a0b[PF], a1b[PF], b0b[PF], b1b[PF], b2b[PF];
#pragma unroll
    for (int p = 0; p < PF; p++) {
        a0b[p] = Ap0[p * 4]; a1b[p] = Ap1[p * 4];
        b0b[p] = Bp0[p * 4]; b1b[p] = Bp1[p * 4]; b2b[p] = Bp2[p * 4];
    }

    for (int s = 0; s < KHALF; s += PF) {
#pragma unroll
        for (int p = 0; p < PF; p++) {
            const uint32_t* A0 = (const uint32_t*)&a0b[p];
            const uint32_t* A1 = (const uint32_t*)&a1b[p];
            const uint32_t* B0 = (const uint32_t*)&b0b[p];
            const uint32_t* B1 = (const uint32_t*)&b1b[p];
            const uint32_t* B2 = (const uint32_t*)&b2b[p];
            mma16816(acc[0].x, acc[0].y, acc[0].z, acc[0].w,
                     A0[0], A1[0], A0[1], A1[1], B0[0], B0[1]);
            mma16816(acc[1].x, acc[1].y, acc[1].z, acc[1].w,
                     A0[0], A1[0], A0[1], A1[1], B1[0], B1[1]);
            mma16816(acc[2].x, acc[2].y, acc[2].z, acc[2].w,
                     A0[0], A1[0], A0[1], A1[1], B2[0], B2[1]);
            mma16816(acc[0].x, acc[0].y, acc[0].z, acc[0].w,
                     A0[2], A1[2], A0[3], A1[3], B0[2], B0[3]);
            mma16816(acc[1].x, acc[1].y, acc[1].z, acc[1].w,
                     A0[2], A1[2], A0[3], A1[3], B1[2], B1[3]);
            mma16816(acc[2].x, acc[2].y, acc[2].z, acc[2].w,
                     A0[2], A1[2], A0[3], A1[3], B2[2], B2[3]);
            // unconditional reload (clamped index; tail loads are discarded)
            int sn = s + p + PF;
            int sfx = (sn < KHALF) ? sn * 4 : 0;
            a0b[p] = Ap0[sfx]; a1b[p] = Ap1[sfx];
            b0b[p] = Bp0[sfx]; b1b[p] = Bp1[sfx]; b2b[p] = Bp2[sfx];
        }
    }

    // scatter fragments: c0=(g,2q), c1=(g,2q+1), c2=(g+8,2q), c3=(g+8,2q+1)
    const int r0 = 16 * w8 + g;
#pragma unroll
    for (int t = 0; t < 3; t++) {
        const int c = 8 * t + 2 * q;
        Ds[kset][r0][c]     = acc[t].x;  Ds[kset][r0][c + 1]     = acc[t].y;
        Ds[kset][r0 + 8][c] = acc[t].z;  Ds[kset][r0 + 8][c + 1] = acc[t].w;
    }
    __syncthreads();

    // ---- fused epilogue: 128 threads, one pixel each ----
    if (tid < 128) {
        const int n = nb + tid;
        const float inv = g_inv[b * NT + n];
        const float* e0p = E0 + (size_t)b * LCH * NT + n;

        float pot[LCH], mn = 3.4e38f;
#pragma unroll
        for (int l = 0; l < LCH; l++) {
            float d = Ds[0][tid][l] + Ds[1][tid][l];
            pot[l] = e0p[(size_t)l * NT] + d * inv;
            mn = fminf(mn, pot[l]);
        }
        float s = 0.f;
#pragma unroll
        for (int l = 0; l < LCH; l++) { pot[l] = fexp2(1.44269504f * (mn - pot[l])); s += pot[l]; }
        float is = 1.f / s;
#pragma unroll
        for (int l = 0; l < LCH; l++) pot[l] *= is;

        if (last) {
            float* o = out + (size_t)b * LCH * NT + n;
#pragma unroll
            for (int l = 0; l < LCH; l++) o[(size_t)l * NT] = pot[l];
        } else {
#pragma unroll
            for (int k = 0; k < LCH; k++) {
                float a = 0.f;
#pragma unroll
                for (int l = 0; l < LCH; l++) a = fmaf(mu_s[k * LCH + l], pot[l], a);
                g_Mt[((size_t)b * LROWS + k) * NT + n] = __float2bfloat16(a);
            }
        }
    }
}

// ============================================================================
extern "C" void kernel_launch(void* const* d_in, const int* in_sizes, int n_in,
                              void* d_out, int out_size) {
    const float* E0   = (const float*)d_in[0];
    const float* Refs = (const float*)d_in[1];
    const float* Mu   = (const float*)d_in[2];
    float* out = (float*)d_out;

    k_affinity<<<(BB * NT) / 32, 256>>>(Refs);
    k_softmax0<<<(BB * NT) / 256, 256>>>(E0, Mu);
    for (int it = 0; it < NITERS; it++)
        k_iter<<<BB * (NT / 128), 512>>>(E0, Mu, out, it == NITERS - 1);
}

// round 7
// speedup vs baseline: 8.1909x; 1.4017x over previous
#include <cuda_runtime.h>
#include <cuda_bf16.h>
#include <cuda_fp8.h>
#include <cstdint>
#include <cstddef>

#define NT    9216
#define LCH   21
#define BB    2
#define NITERS 5
#define LROWS 24            // padded label rows for MMA (3 x n8)
#define K64S  (NT / 64)     // 144 k64 superstep-pairs
#define KH    (K64S / 2)    // 72 per warp-set
#define PF    4             // prefetch depth

// ---------------- device scratch (no allocation allowed) ----------------
__device__ uint8_t g_Af8[(size_t)BB * NT * NT];   // ~162 MB, e4m3, row-major [n][m]
__device__ float   g_inv[BB * NT];                // 1 / rowsum (of dequantized fp8)
__device__ uint8_t g_Mf8[(size_t)BB * LROWS * NT];// M^T e4m3: [b][l][m], rows 21..23 zero

// ---------------- helpers ----------------
__device__ __forceinline__ float ex2f(float x) {
    float y; asm("ex2.approx.f32 %0, %1;" : "=f"(y) : "f"(x)); return y;
}
// fp32 exp2 poly for epilogue softmax (keeps softmax exact-ish independent of MUFU)
__device__ __forceinline__ float fexp2(float y) {
    float r = y + 12582912.0f;
    float f = y - (r - 12582912.0f);
    int   n = __float_as_int(r);
    float s = __int_as_float((n + (127 - 0x4B400000)) << 23);
    float p = fmaf(0.00961813f, f, 0.05550411f);
    p = fmaf(p, f, 0.24022651f);
    p = fmaf(p, f, 0.69314718f);
    p = fmaf(p, f, 1.0f);
    return p * s;
}
__device__ __forceinline__ uint8_t to_fp8(float v) {
    return (uint8_t)__nv_cvt_float_to_fp8(v, __NV_SATFINITE, __NV_E4M3);
}

// ============================================================================
// Kernel 1: affinity (e4m3) + rowsum reciprocal of DEQUANTIZED values.
// 32 rows / block, 576 blocks. exp on MUFU (ex2.approx), dot on FMA pipe.
// ============================================================================
__global__ __launch_bounds__(256) void k_affinity(const float* __restrict__ Refs) {
    __shared__ float4 rf[32];
    __shared__ float  wsum[8][33];
    const int tid = threadIdx.x;
    const int R = blockIdx.x * 32;
    const int b = R / NT;
    const int n0 = R - b * NT;
    const float* F = Refs + (size_t)b * 3 * NT;

    if (tid < 32) {
        int n = n0 + tid;
        float x = F[n], y = F[NT + n], z = F[2 * NT + n];
        rf[tid] = make_float4(x, y, z, -0.72134752f * (x * x + y * y + z * z));
    }
    __syncthreads();

    float part[32];
#pragma unroll
    for (int r = 0; r < 32; r++) part[r] = 0.f;

    for (int m2 = tid; m2 < NT / 2; m2 += 256) {
        int m = m2 * 2;
        float x0 = F[m],     y0 = F[NT + m],     z0 = F[2 * NT + m];
        float x1 = F[m + 1], y1 = F[NT + m + 1], z1 = F[2 * NT + m + 1];
        float sc0 = -0.72134752f * (x0 * x0 + y0 * y0 + z0 * z0);
        float sc1 = -0.72134752f * (x1 * x1 + y1 * y1 + z1 * z1);
#pragma unroll
        for (int r = 0; r < 32; r++) {
            float4 f = rf[r];
            float d0 = x0 * f.x + y0 * f.y + z0 * f.z;
            float d1 = x1 * f.x + y1 * f.y + z1 * f.z;
            float e0 = ex2f(fmaf(d0, 1.44269504f, f.w + sc0));
            float e1 = ex2f(fmaf(d1, 1.44269504f, f.w + sc1));
            __nv_fp8x2_storage_t p2 =
                __nv_cvt_float2_to_fp8x2(make_float2(e0, e1), __NV_SATFINITE, __NV_E4M3);
            ((unsigned short*)(g_Af8 + (size_t)(b * NT + n0 + r) * NT))[m2] = p2;
            // accumulate the DEQUANTIZED values for self-consistent normalization
            __half2_raw hr = __nv_cvt_fp8x2_to_halfraw2(p2, __NV_E4M3);
            float2 de = __half22float2(*reinterpret_cast<__half2*>(&hr));
            part[r] += de.x + de.y;
        }
    }

    const int lane = tid & 31, w = tid >> 5;
#pragma unroll
    for (int r = 0; r < 32; r++) {
        float v = part[r];
#pragma unroll
        for (int off = 16; off; off >>= 1) v += __shfl_down_sync(0xffffffffu, v, off);
        if (lane == 0) wsum[w][r] = v;
    }
    __syncthreads();
    if (tid < 32) {
        float s = 0.f;
#pragma unroll
        for (int w2 = 0; w2 < 8; w2++) s += wsum[w2][tid];
        g_inv[b * NT + n0 + tid] = 1.f / s;
    }
}

// ============================================================================
// Kernel 2: initial softmax + Potts mix:  Mt = Mu @ softmax(-E0)  (e4m3)
// ============================================================================
__global__ __launch_bounds__(256) void k_softmax0(const float* __restrict__ E0,
                                                  const float* __restrict__ Mu) {
    __shared__ float mu[LCH * LCH];
    const int tid = threadIdx.x;
    for (int i = tid; i < LCH * LCH; i += 256) mu[i] = Mu[i];
    __syncthreads();

    const int pix = blockIdx.x * 256 + tid;
    const int b = pix / NT;
    const int n = pix - b * NT;
    const float* p = E0 + (size_t)b * LCH * NT + n;

    float v[LCH], mn = 3.4e38f;
#pragma unroll
    for (int l = 0; l < LCH; l++) { v[l] = p[(size_t)l * NT]; mn = fminf(mn, v[l]); }
    float s = 0.f;
#pragma unroll
    for (int l = 0; l < LCH; l++) { v[l] = fexp2(1.44269504f * (mn - v[l])); s += v[l]; }
    float is = 1.f / s;
#pragma unroll
    for (int l = 0; l < LCH; l++) v[l] *= is;

#pragma unroll
    for (int k = 0; k < LCH; k++) {
        float a = 0.f;
#pragma unroll
        for (int l = 0; l < LCH; l++) a = fmaf(mu[k * LCH + l], v[l], a);
        g_Mf8[((size_t)b * LROWS + k) * NT + n] = to_fp8(a);
    }
#pragma unroll
    for (int k = LCH; k < LROWS; k++) g_Mf8[((size_t)b * LROWS + k) * NT + n] = 0;
}

// ---------------- warp-level e4m3 MMA (sm_89+, no 'a' gating) ----------------
__device__ __forceinline__ void mma16832(float& c0, float& c1, float& c2, float& c3,
                                         uint32_t a0, uint32_t a1, uint32_t a2, uint32_t a3,
                                         uint32_t b0, uint32_t b1) {
    asm volatile(
        "mma.sync.aligned.m16n8k32.row.col.f32.e4m3.e4m3.f32 "
        "{%0,%1,%2,%3}, {%4,%5,%6,%7}, {%8,%9}, {%0,%1,%2,%3};"
        : "+f"(c0), "+f"(c1), "+f"(c2), "+f"(c3)
        : "r"(a0), "r"(a1), "r"(a2), "r"(a3), "r"(b0), "r"(b1));
}

// ============================================================================
// Kernel 3: one mean-field iteration via FP8 HMMA, K-split x2 in the CTA.
// 512 thr = 16 warps; warp-set handles one K half (72 k64 pairs).
// Per lane per k64: one LDG.128 per stream; int4 = (slot0_s, slot2_s,
// slot0_s1, slot2_s1) under the implicit K relabeling (identical for A and B).
// ============================================================================
__global__ __launch_bounds__(512, 1) void k_iter(const float* __restrict__ E0,
                                                 const float* __restrict__ Mu,
                                                 float* __restrict__ out, int last) {
    __shared__ float Ds[2][128][25];
    __shared__ float mu_s[LCH * LCH];

    const int tid = threadIdx.x;
    const int wid = tid >> 5, lane = tid & 31;
    const int kset = wid >> 3, w8 = wid & 7;
    const int g = lane >> 2, q = lane & 3;
    const int b  = blockIdx.x / (NT / 128);
    const int nb = (blockIdx.x - b * (NT / 128)) * 128;

    for (int i = tid; i < LCH * LCH; i += 512) mu_s[i] = Mu[i];

    // int4 index per k64 pair s: 4*s + q ; K-half offset = kset*KH pairs
    const int rowA = nb + 16 * w8 + g;
    const int ko = kset * KH * 4 + q;
    const int4* Ap0 = (const int4*)(g_Af8 + (size_t)(b * NT + rowA) * NT) + ko;
    const int4* Ap1 = (const int4*)(g_Af8 + (size_t)(b * NT + rowA + 8) * NT) + ko;
    const int4* Bp0 = (const int4*)(g_Mf8 + (size_t)(b * LROWS + g)      * NT) + ko;
    const int4* Bp1 = (const int4*)(g_Mf8 + (size_t)(b * LROWS + 8 + g)  * NT) + ko;
    const int4* Bp2 = (const int4*)(g_Mf8 + (size_t)(b * LROWS + 16 + g) * NT) + ko;

    float4 acc[3];
#pragma unroll
    for (int t = 0; t < 3; t++) acc[t] = make_float4(0.f, 0.f, 0.f, 0.f);

    int4 a0b[PF], a1b[PF], b0b[PF], b1b[PF], b2b[PF];
#pragma unroll
    for (int p = 0; p < PF; p++) {
        a0b[p] = Ap0[p * 4]; a1b[p] = Ap1[p * 4];
        b0b[p] = Bp0[p * 4]; b1b[p] = Bp1[p * 4]; b2b[p] = Bp2[p * 4];
    }

    for (int s = 0; s < KH; s += PF) {
#pragma unroll
        for (int p = 0; p < PF; p++) {
            const uint32_t* A0 = (const uint32_t*)&a0b[p];
            const uint32_t* A1 = (const uint32_t*)&a1b[p];
            const uint32_t* B0 = (const uint32_t*)&b0b[p];
            const uint32_t* B1 = (const uint32_t*)&b1b[p];
            const uint32_t* B2 = (const uint32_t*)&b2b[p];
            // k32 step s of the pair
            mma16832(acc[0].x, acc[0].y, acc[0].z, acc[0].w,
                     A0[0], A1[0], A0[1], A1[1], B0[0], B0[1]);
            mma16832(acc[1].x, acc[1].y, acc[1].z, acc[1].w,
                     A0[0], A1[0], A0[1], A1[1], B1[0], B1[1]);
            mma16832(acc[2].x, acc[2].y, acc[2].z, acc[2].w,
                     A0[0], A1[0], A0[1], A1[1], B2[0], B2[1]);
            // k32 step s+1 of the pair
            mma16832(acc[0].x, acc[0].y, acc[0].z, acc[0].w,
                     A0[2], A1[2], A0[3], A1[3], B0[2], B0[3]);
            mma16832(acc[1].x, acc[1].y, acc[1].z, acc[1].w,
                     A0[2], A1[2], A0[3], A1[3], B1[2], B1[3]);
            mma16832(acc[2].x, acc[2].y, acc[2].z, acc[2].w,
                     A0[2], A1[2], A0[3], A1[3], B2[2], B2[3]);
            // unconditional reload (clamped index; tail loads discarded)
            int sn = s + p + PF;
            int sfx = (sn < KH) ? sn * 4 : 0;
            a0b[p] = Ap0[sfx]; a1b[p] = Ap1[sfx];
            b0b[p] = Bp0[sfx]; b1b[p] = Bp1[sfx]; b2b[p] = Bp2[sfx];
        }
    }

    // scatter fragments: c0=(g,2q), c1=(g,2q+1), c2=(g+8,2q), c3=(g+8,2q+1)
    const int r0 = 16 * w8 + g;
#pragma unroll
    for (int t = 0; t < 3; t++) {
        const int c = 8 * t + 2 * q;
        Ds[kset][r0][c]     = acc[t].x;  Ds[kset][r0][c + 1]     = acc[t].y;
        Ds[kset][r0 + 8][c] = acc[t].z;  Ds[kset][r0 + 8][c + 1] = acc[t].w;
    }
    __syncthreads();

    // ---- fused epilogue: 128 threads, one pixel each ----
    if (tid < 128) {
        const int n = nb + tid;
        const float inv = g_inv[b * NT + n];
        const float* e0p = E0 + (size_t)b * LCH * NT + n;

        float pot[LCH], mn = 3.4e38f;
#pragma unroll
        for (int l = 0; l < LCH; l++) {
            float d = Ds[0][tid][l] + Ds[1][tid][l];
            pot[l] = e0p[(size_t)l * NT] + d * inv;
            mn = fminf(mn, pot[l]);
        }
        float s = 0.f;
#pragma unroll
        for (int l = 0; l < LCH; l++) { pot[l] = fexp2(1.44269504f * (mn - pot[l])); s += pot[l]; }
        float is = 1.f / s;
#pragma unroll
        for (int l = 0; l < LCH; l++) pot[l] *= is;

        if (last) {
            float* o = out + (size_t)b * LCH * NT + n;
#pragma unroll
            for (int l = 0; l < LCH; l++) o[(size_t)l * NT] = pot[l];
        } else {
#pragma unroll
            for (int k = 0; k < LCH; k++) {
                float a = 0.f;
#pragma unroll
                for (int l = 0; l < LCH; l++) a = fmaf(mu_s[k * LCH + l], pot[l], a);
                g_Mf8[((size_t)b * LROWS + k) * NT + n] = to_fp8(a);
            }
        }
    }
}

// ============================================================================
extern "C" void kernel_launch(void* const* d_in, const int* in_sizes, int n_in,
                              void* d_out, int out_size) {
    const float* E0   = (const float*)d_in[0];
    const float* Refs = (const float*)d_in[1];
    const float* Mu   = (const float*)d_in[2];
    float* out = (float*)d_out;

    k_affinity<<<(BB * NT) / 32, 256>>>(Refs);
    k_softmax0<<<(BB * NT) / 256, 256>>>(E0, Mu);
    for (int it = 0; it < NITERS; it++)
        k_iter<<<BB * (NT / 128), 512>>>(E0, Mu, out, it == NITERS - 1);
}